// round 3
// baseline (speedup 1.0000x reference)
#include <cuda_runtime.h>

#define RES 256
#define CELLS (RES*RES)
#define NCH 32
#define ACCSZ (CELLS*NCH)
#define NPLANE 3

// Scratch (device globals: allocation-free rule)
__device__ float  g_acc [NPLANE*ACCSZ];   // [plane][cell][ch]
__device__ float  g_cnt [NPLANE*CELLS];   // [plane][cell]
__device__ float  g_newT[NPLANE*ACCSZ];   // [plane][ch][cell]  (transposed, pre-LN)
__device__ double g_sum [NPLANE];
__device__ double g_ss  [NPLANE];

// ---------------------------------------------------------------- zero
__global__ void k_zero() {
    int i = blockIdx.x * blockDim.x + threadIdx.x;
    int stride = gridDim.x * blockDim.x;
    for (int j = i; j < NPLANE*ACCSZ; j += stride) g_acc[j] = 0.f;
    for (int j = i; j < NPLANE*CELLS; j += stride) g_cnt[j] = 0.f;
    if (i < NPLANE) { g_sum[i] = 0.0; g_ss[i] = 0.0; }
}

// ---------------------------------------------------------------- scatter
// one warp per gaussian; lane = (corner, 4-ch group). One red.v4.f32 per lane
// per plane: 48M vector atomics instead of 192M scalar ones.
__global__ void k_scatter(const float* __restrict__ xyz,
                          const float* __restrict__ feats, int n) {
    int w    = (blockIdx.x * blockDim.x + threadIdx.x) >> 5;
    int lane = threadIdx.x & 31;
    if (w >= n) return;

    int corner = lane >> 3;   // 0..3
    int cg     = lane & 7;    // 4-channel group

    float gx = __ldg(xyz + 3*w + 0);
    float gy = __ldg(xyz + 3*w + 1);
    float gz = __ldg(xyz + 3*w + 2);
    float x = fminf(fmaxf((gx + 1.f) * 0.5f, 0.f), 0.999f) * (float)(RES - 1);
    float y = fminf(fmaxf((gy + 1.f) * 0.5f, 0.f), 0.999f) * (float)(RES - 1);
    float z = fminf(fmaxf((gz + 1.f) * 0.5f, 0.f), 0.999f) * (float)(RES - 1);

    #pragma unroll
    for (int p = 0; p < 3; p++) {
        float px = (p == 2) ? y : x;              // xy:(x,y) xz:(x,z) yz:(y,z)
        float py = (p == 0) ? y : z;

        int ix0 = (int)floorf(px);
        int iy0 = (int)floorf(py);
        int ix0c = min(max(ix0, 0), RES-1);
        int ix1c = min(ix0 + 1,    RES-1);
        int iy0c = min(max(iy0, 0), RES-1);
        int iy1c = min(iy0 + 1,    RES-1);

        float wx0 = fminf(fmaxf((float)ix1c - px, 0.f), 1.f);
        float wx1 = fminf(fmaxf(px - (float)ix0c, 0.f), 1.f);
        float wy0 = fminf(fmaxf((float)iy1c - py, 0.f), 1.f);
        float wy1 = fminf(fmaxf(py - (float)iy0c, 0.f), 1.f);

        // corner 0:(x0,y0) 1:(x0,y1) 2:(x1,y0) 3:(x1,y1) — matches ref weight order
        int   l  = ((corner & 1) ? iy1c : iy0c) * RES + ((corner >> 1) ? ix1c : ix0c);
        float wc = ((corner >> 1) ? wx1 : wx0) * ((corner & 1) ? wy1 : wy0);

        float4 f = *(const float4*)(feats + (size_t)w*96 + p*32 + cg*4);
        float* dst = g_acc + (size_t)p*ACCSZ + (size_t)l*NCH + cg*4;
        asm volatile("red.global.add.v4.f32 [%0], {%1,%2,%3,%4};"
                     :: "l"(dst), "f"(f.x*wc), "f"(f.y*wc), "f"(f.z*wc), "f"(f.w*wc)
                     : "memory");

        if (cg == 0) atomicAdd(g_cnt + p*CELLS + l, 1.0f);
    }
}

// ---------------------------------------------------------------- reduce + transpose
// thread per cell: divide by counts, write channel-major newT, accumulate sum/sumsq
__global__ void k_reduce() {
    int p    = blockIdx.y;
    int cell = blockIdx.x * blockDim.x + threadIdx.x;

    float cnt = g_cnt[p*CELLS + cell];
    float inv = 1.f / (cnt + 1e-6f);
    const float4* a = (const float4*)(g_acc + (size_t)p*ACCSZ + (size_t)cell*NCH);
    float* nt = g_newT + (size_t)p*ACCSZ;

    float s = 0.f, ss = 0.f;
    #pragma unroll
    for (int i = 0; i < 8; i++) {
        float4 v = a[i];
        float n0 = v.x*inv, n1 = v.y*inv, n2 = v.z*inv, n3 = v.w*inv;
        s  += n0 + n1 + n2 + n3;
        ss += n0*n0 + n1*n1 + n2*n2 + n3*n3;
        nt[(size_t)(i*4+0)*CELLS + cell] = n0;
        nt[(size_t)(i*4+1)*CELLS + cell] = n1;
        nt[(size_t)(i*4+2)*CELLS + cell] = n2;
        nt[(size_t)(i*4+3)*CELLS + cell] = n3;
    }

    double ds = (double)s, dss = (double)ss;
    #pragma unroll
    for (int off = 16; off; off >>= 1) {
        ds  += __shfl_down_sync(0xFFFFFFFFu, ds,  off);
        dss += __shfl_down_sync(0xFFFFFFFFu, dss, off);
    }
    __shared__ double shs[8], shss[8];
    int wid = threadIdx.x >> 5;
    if ((threadIdx.x & 31) == 0) { shs[wid] = ds; shss[wid] = dss; }
    __syncthreads();
    if (threadIdx.x == 0) {
        double t = 0.0, tt = 0.0;
        for (int i = 0; i < 8; i++) { t += shs[i]; tt += shss[i]; }
        atomicAdd(&g_sum[p], t);
        atomicAdd(&g_ss[p], tt);
    }
}

// ---------------------------------------------------------------- normalize + blur + residual
// (LN stats finalized inline — no separate k_finalize launch)
__global__ void k_blur(const float* __restrict__ p_xy,
                       const float* __restrict__ p_xz,
                       const float* __restrict__ p_yz,
                       const float* __restrict__ lnw,
                       const float* __restrict__ lnb,
                       float* __restrict__ out) {
    const float W0 = 0.054488684549642945f;
    const float W1 = 0.2442013422000340f;
    const float W2 = 0.4026199464998460f;

    int zc = blockIdx.z;
    int p = zc >> 5;
    int c = zc & 31;

    double nelem = (double)ACCSZ;
    double mu_d  = g_sum[p] / nelem;
    double var_d = g_ss[p] / nelem - mu_d * mu_d;
    float mu  = (float)mu_d;
    float inv = (float)(1.0 / sqrt(var_d + 1e-5));

    const float* nt  = g_newT + (size_t)p*ACCSZ + (size_t)c*CELLS;
    const float* lw  = lnw + (size_t)c*CELLS;
    const float* lb  = lnb + (size_t)c*CELLS;

    __shared__ float raw[36][40];
    __shared__ float ht [36][32];

    int tid = threadIdx.y * 32 + threadIdx.x;
    int gx0 = blockIdx.x * 32 - 2;
    int gy0 = blockIdx.y * 32 - 2;

    for (int idx = tid; idx < 36*36; idx += 256) {
        int r  = idx / 36;
        int cc = idx - r*36;
        int gy = gy0 + r, gx = gx0 + cc;
        float v = 0.f;
        if ((unsigned)gy < (unsigned)RES && (unsigned)gx < (unsigned)RES) {
            int lin = gy*RES + gx;
            v = (nt[lin] - mu) * inv * lw[lin] + lb[lin];
        }
        raw[r][cc] = v;
    }
    __syncthreads();

    for (int idx = tid; idx < 36*32; idx += 256) {
        int r  = idx >> 5;
        int cc = idx & 31;
        ht[r][cc] = W0*(raw[r][cc]   + raw[r][cc+4])
                  + W1*(raw[r][cc+1] + raw[r][cc+3])
                  + W2* raw[r][cc+2];
    }
    __syncthreads();

    const float* plane = (p == 0) ? p_xy : (p == 1) ? p_xz : p_yz;
    int gx = blockIdx.x * 32 + threadIdx.x;
    #pragma unroll
    for (int k = 0; k < 4; k++) {
        int ty = threadIdx.y + k*8;
        int gy = blockIdx.y * 32 + ty;
        float o = W0*(ht[ty  ][threadIdx.x] + ht[ty+4][threadIdx.x])
                + W1*(ht[ty+1][threadIdx.x] + ht[ty+3][threadIdx.x])
                + W2* ht[ty+2][threadIdx.x];
        size_t off = (size_t)c*CELLS + (size_t)gy*RES + gx;
        out[(size_t)p*ACCSZ + off] = o + plane[off];
    }
}

// ---------------------------------------------------------------- launch
extern "C" void kernel_launch(void* const* d_in, const int* in_sizes, int n_in,
                              void* d_out, int out_size) {
    const float* plane_xy = (const float*)d_in[0];
    const float* plane_xz = (const float*)d_in[1];
    const float* plane_yz = (const float*)d_in[2];
    const float* ln_w     = (const float*)d_in[3];
    const float* ln_b     = (const float*)d_in[4];
    const float* feats    = (const float*)d_in[5];
    const float* xyz      = (const float*)d_in[6];
    float* out = (float*)d_out;
    int n = in_sizes[6] / 3;   // 500000

    k_zero<<<1024, 256>>>();
    {
        int threads = 256;
        long long total = (long long)n * 32;
        int blocks = (int)((total + threads - 1) / threads);
        k_scatter<<<blocks, threads>>>(xyz, feats, n);
    }
    k_reduce<<<dim3(CELLS/256, NPLANE), 256>>>();
    k_blur<<<dim3(RES/32, RES/32, NPLANE*NCH), dim3(32, 8)>>>(
        plane_xy, plane_xz, plane_yz, ln_w, ln_b, out);
}

// round 6
// speedup vs baseline: 1.0094x; 1.0094x over previous
#include <cuda_runtime.h>

#define RES 256
#define CELLS (RES*RES)
#define NCH 32
#define ACCSZ (CELLS*NCH)
#define NPLANE 3

// Scratch (device globals: allocation-free rule)
__device__ float  g_acc [NPLANE*ACCSZ];   // [plane][cell][ch]
__device__ float  g_cnt [NPLANE*CELLS];   // [plane][cell]
__device__ float  g_newT[NPLANE*ACCSZ];   // [plane][ch][cell]  (transposed, pre-LN)
__device__ double g_sum [NPLANE];
__device__ double g_ss  [NPLANE];

// ---------------------------------------------------------------- zero (float4)
__global__ void k_zero() {
    int i = blockIdx.x * blockDim.x + threadIdx.x;
    int stride = gridDim.x * blockDim.x;
    float4 z = make_float4(0.f, 0.f, 0.f, 0.f);
    float4* a = (float4*)g_acc;
    float4* c = (float4*)g_cnt;
    for (int j = i; j < NPLANE*ACCSZ/4; j += stride) a[j] = z;
    for (int j = i; j < NPLANE*CELLS/4; j += stride) c[j] = z;
    if (i < NPLANE) { g_sum[i] = 0.0; g_ss[i] = 0.0; }
}

// ---------------------------------------------------------------- scatter
// one warp per gaussian; lane = channel. 4 coalesced 128B RED lines per plane.
// (R2 form — measured fastest; LTS byte-bound)
__global__ void k_scatter(const float* __restrict__ xyz,
                          const float* __restrict__ feats, int n) {
    int w    = (blockIdx.x * blockDim.x + threadIdx.x) >> 5;
    int lane = threadIdx.x & 31;
    if (w >= n) return;

    float gx = __ldg(xyz + 3*w + 0);
    float gy = __ldg(xyz + 3*w + 1);
    float gz = __ldg(xyz + 3*w + 2);
    float x = fminf(fmaxf((gx + 1.f) * 0.5f, 0.f), 0.999f) * (float)(RES - 1);
    float y = fminf(fmaxf((gy + 1.f) * 0.5f, 0.f), 0.999f) * (float)(RES - 1);
    float z = fminf(fmaxf((gz + 1.f) * 0.5f, 0.f), 0.999f) * (float)(RES - 1);

    #pragma unroll
    for (int p = 0; p < 3; p++) {
        float px = (p == 2) ? y : x;              // xy:(x,y) xz:(x,z) yz:(y,z)
        float py = (p == 0) ? y : z;

        int ix0 = (int)floorf(px);
        int iy0 = (int)floorf(py);
        int ix0c = min(max(ix0, 0), RES-1);
        int ix1c = min(ix0 + 1,    RES-1);
        int iy0c = min(max(iy0, 0), RES-1);
        int iy1c = min(iy0 + 1,    RES-1);

        float wx0 = fminf(fmaxf((float)ix1c - px, 0.f), 1.f);
        float wx1 = fminf(fmaxf(px - (float)ix0c, 0.f), 1.f);
        float wy0 = fminf(fmaxf((float)iy1c - py, 0.f), 1.f);
        float wy1 = fminf(fmaxf(py - (float)iy0c, 0.f), 1.f);

        int l0 = iy0c*RES + ix0c;
        int l1 = iy1c*RES + ix0c;
        int l2 = iy0c*RES + ix1c;
        int l3 = iy1c*RES + ix1c;
        float w00 = wx0*wy0, w01 = wx0*wy1, w10 = wx1*wy0, w11 = wx1*wy1;

        float f = __ldg(feats + (size_t)w*96 + p*32 + lane);
        float* base = g_acc + (size_t)p*ACCSZ;
        atomicAdd(base + (size_t)l0*NCH + lane, f*w00);
        atomicAdd(base + (size_t)l1*NCH + lane, f*w01);
        atomicAdd(base + (size_t)l2*NCH + lane, f*w10);
        atomicAdd(base + (size_t)l3*NCH + lane, f*w11);

        if (lane < 4) {
            int ll = (lane == 0) ? l0 : (lane == 1) ? l1 : (lane == 2) ? l2 : l3;
            atomicAdd(g_cnt + p*CELLS + ll, 1.0f);
        }
    }
}

// ---------------------------------------------------------------- reduce + transpose
__global__ void k_reduce() {
    int p    = blockIdx.y;
    int cell = blockIdx.x * blockDim.x + threadIdx.x;

    float cnt = g_cnt[p*CELLS + cell];
    float inv = 1.f / (cnt + 1e-6f);
    const float4* a = (const float4*)(g_acc + (size_t)p*ACCSZ + (size_t)cell*NCH);
    float* nt = g_newT + (size_t)p*ACCSZ;

    float s = 0.f, ss = 0.f;
    #pragma unroll
    for (int i = 0; i < 8; i++) {
        float4 v = a[i];
        float n0 = v.x*inv, n1 = v.y*inv, n2 = v.z*inv, n3 = v.w*inv;
        s  += n0 + n1 + n2 + n3;
        ss += n0*n0 + n1*n1 + n2*n2 + n3*n3;
        nt[(size_t)(i*4+0)*CELLS + cell] = n0;
        nt[(size_t)(i*4+1)*CELLS + cell] = n1;
        nt[(size_t)(i*4+2)*CELLS + cell] = n2;
        nt[(size_t)(i*4+3)*CELLS + cell] = n3;
    }

    double ds = (double)s, dss = (double)ss;
    #pragma unroll
    for (int off = 16; off; off >>= 1) {
        ds  += __shfl_down_sync(0xFFFFFFFFu, ds,  off);
        dss += __shfl_down_sync(0xFFFFFFFFu, dss, off);
    }
    __shared__ double shs[8], shss[8];
    int wid = threadIdx.x >> 5;
    if ((threadIdx.x & 31) == 0) { shs[wid] = ds; shss[wid] = dss; }
    __syncthreads();
    if (threadIdx.x == 0) {
        double t = 0.0, tt = 0.0;
        for (int i = 0; i < 8; i++) { t += shs[i]; tt += shss[i]; }
        atomicAdd(&g_sum[p], t);
        atomicAdd(&g_ss[p], tt);
    }
}

// ---------------------------------------------------------------- normalize + blur + residual
// Column-sliding blur: block = 256 threads = full image width, one (p,c,strip).
// Horizontal 5-tap via double-buffered smem row (1 sync/row); vertical 5-tap
// in a rolling register window; LN affine fused at load; residual fused at store.
#define STRIP 32
__global__ void k_blur(const float* __restrict__ p_xy,
                       const float* __restrict__ p_xz,
                       const float* __restrict__ p_yz,
                       const float* __restrict__ lnw,
                       const float* __restrict__ lnb,
                       float* __restrict__ out) {
    const float W0 = 0.054488684549642945f;
    const float W1 = 0.2442013422000340f;
    const float W2 = 0.4026199464998460f;

    int pc = blockIdx.y;
    int p  = pc >> 5;
    int c  = pc & 31;
    int x  = threadIdx.x;

    double nelem = (double)ACCSZ;
    double mu_d  = g_sum[p] / nelem;
    double var_d = g_ss[p] / nelem - mu_d * mu_d;
    float mu  = (float)mu_d;
    float inv = (float)(1.0 / sqrt(var_d + 1e-5));

    const float* nt    = g_newT + (size_t)p*ACCSZ + (size_t)c*CELLS;
    const float* lw    = lnw + (size_t)c*CELLS;
    const float* lb    = lnb + (size_t)c*CELLS;
    const float* plane = ((p == 0) ? p_xy : (p == 1) ? p_xz : p_yz) + (size_t)c*CELLS;
    float*       o     = out + (size_t)p*ACCSZ + (size_t)c*CELLS;

    __shared__ float s[2][260];
    if (x < 2)    { s[0][x] = 0.f;     s[1][x] = 0.f; }
    if (x >= 254) { s[0][x + 4] = 0.f; s[1][x + 4] = 0.f; }

    int y0 = blockIdx.x * STRIP;

    // LN'd row load (0 outside image)
    auto loadrow = [&](int y) -> float {
        if ((unsigned)y < (unsigned)RES) {
            int lin = y*RES + x;
            return (nt[lin] - mu) * inv * lw[lin] + lb[lin];
        }
        return 0.f;
    };

    // 2-stage register prefetch pipeline
    float vA = loadrow(y0 - 2);
    float vB = loadrow(y0 - 1);

    float h0 = 0.f, h1 = 0.f, h2 = 0.f, h3 = 0.f, h4 = 0.f;
    int parity = 0;

    #pragma unroll 4
    for (int i = 0; i < STRIP + 4; i++) {
        int yh = y0 - 2 + i;
        float v = vA;
        vA = vB;
        vB = loadrow(yh + 2);

        s[parity][x + 2] = v;
        __syncthreads();
        float h = W0*(s[parity][x]   + s[parity][x+4])
                + W1*(s[parity][x+1] + s[parity][x+3])
                + W2* s[parity][x+2];
        parity ^= 1;

        h0 = h1; h1 = h2; h2 = h3; h3 = h4; h4 = h;

        if (i >= 4) {
            int yo = yh - 2;
            float r = W0*(h0 + h4) + W1*(h1 + h3) + W2*h2;
            int lin = yo*RES + x;
            o[lin] = r + plane[lin];
        }
    }
}

// ---------------------------------------------------------------- launch
extern "C" void kernel_launch(void* const* d_in, const int* in_sizes, int n_in,
                              void* d_out, int out_size) {
    const float* plane_xy = (const float*)d_in[0];
    const float* plane_xz = (const float*)d_in[1];
    const float* plane_yz = (const float*)d_in[2];
    const float* ln_w     = (const float*)d_in[3];
    const float* ln_b     = (const float*)d_in[4];
    const float* feats    = (const float*)d_in[5];
    const float* xyz      = (const float*)d_in[6];
    float* out = (float*)d_out;
    int n = in_sizes[6] / 3;   // 500000

    k_zero<<<1024, 256>>>();
    {
        int threads = 256;
        long long total = (long long)n * 32;
        int blocks = (int)((total + threads - 1) / threads);
        k_scatter<<<blocks, threads>>>(xyz, feats, n);
    }
    k_reduce<<<dim3(CELLS/256, NPLANE), 256>>>();
    k_blur<<<dim3(RES/STRIP, NPLANE*NCH), 256>>>(
        plane_xy, plane_xz, plane_yz, ln_w, ln_b, out);
}